// round 10
// baseline (speedup 1.0000x reference)
#include <cuda_runtime.h>
#include <cstdint>

// ---------------------------------------------------------------------------
// LaneAttention: per-lane MLP score -> per-group(8) softmax -> weighted pool
// M = 262144 lanes, groups of 8 contiguous lanes, N = 32768, out [N,192]
//
// R10 = R9 (TPB=128, grid=2048, 7 CTAs/SM balanced waves, weights in the
// constant bank, phase-2 pooling from L2) with the barrier structure halved:
//   * 3-buffer cp.async pipeline, ONE __syncthreads per chunk (8 total)
//   * final block barrier removed (phase 2 is warp-local: per-warp outrow,
//     __syncwarp only)
// ---------------------------------------------------------------------------

static constexpr int TPB = 128;        // threads = rows per block
static constexpr int CS  = 5;          // buffer row stride in float4 (4 data + 1 pad)
static constexpr int CHUNK_F4 = TPB * CS;            // 640 float4 per buffer
static constexpr int NBUF = 3;

__constant__ float cW1[128 * 16];      // 8 KB

__device__ __forceinline__ unsigned long long pack_dup(float x) {
    unsigned long long r;
    asm("mov.b64 %0, {%1, %1};" : "=l"(r) : "f"(x));
    return r;
}
__device__ __forceinline__ unsigned long long pack_xy(float x, float y) {
    unsigned long long r;
    asm("mov.b64 %0, {%1, %2};" : "=l"(r) : "f"(x), "f"(y));
    return r;
}
__device__ __forceinline__ void ffma2(unsigned long long &d, unsigned long long a, unsigned long long b) {
    asm("fma.rn.f32x2 %0, %1, %2, %0;" : "+l"(d) : "l"(a), "l"(b));
}
__device__ __forceinline__ float2 unpack2(unsigned long long v) {
    float2 f;
    asm("mov.b64 {%0, %1}, %2;" : "=f"(f.x), "=f"(f.y) : "l"(v));
    return f;
}
__device__ __forceinline__ void cp_async16(uint32_t dst_smem, const void* src) {
    asm volatile("cp.async.cg.shared.global [%0], [%1], 16;\n"
                 :: "r"(dst_smem), "l"(src) : "memory");
}
__device__ __forceinline__ void cp_commit() {
    asm volatile("cp.async.commit_group;\n");
}
template <int N>
__device__ __forceinline__ void cp_wait() {
    asm volatile("cp.async.wait_group %0;\n" :: "n"(N) : "memory");
}

extern __shared__ float smem_f[];
// layout (floats): xbuf 3*640*4 = 7680 | probs 128 | outrow 16 ints
static constexpr int PROBS_OFF  = NBUF * CHUNK_F4 * 4;              // 7680
static constexpr int SMEM_BYTES = (PROBS_OFF + TPB) * 4 + 128;      // ~31.4 KB

// stage 16 columns (4 float4) of all 128 rows of `arr` chunk cc&3 into buffer b
__device__ __forceinline__ void stage_chunk(const float* arr, int row0, int cc,
                                            int b, int tid, uint32_t smem_base)
{
    const float4* src = (const float4*)(arr + (size_t)row0 * 64) + (cc & 3) * 4;
    #pragma unroll
    for (int u = 0; u < 4; ++u) {
        int f = tid + TPB * u;          // flat float4 idx 0..511
        int r = f >> 2, c = f & 3;
        cp_async16(smem_base + (uint32_t)(b * CHUNK_F4 + r * CS + c) * 16u,
                   src + r * 16 + c);
    }
    cp_commit();
}

__global__ __launch_bounds__(TPB, 7)
void lane_attn_kernel(const float* __restrict__ ht,
                      const float* __restrict__ info,
                      const float* __restrict__ fut,
                      const float* __restrict__ b1,   // [16]
                      const float* __restrict__ W2,   // [16]
                      const float* __restrict__ b2,   // [1]
                      const int*   __restrict__ seg,  // [M]
                      float* __restrict__ out)        // [N,192]
{
    float*  probs  = smem_f + PROBS_OFF;
    int*    outrow = (int*)(probs + TPB);
    const float4* xbuf4 = (const float4*)smem_f;

    const int tid  = threadIdx.x;
    const int wrp  = tid >> 5;
    const int lane = tid & 31;
    const int row0 = blockIdx.x * TPB;
    const uint32_t xb_s = (uint32_t)__cvta_generic_to_shared(smem_f);

    // prime the pipeline: chunks 0,1 in flight
    stage_chunk(ht, row0, 0, 0, tid, xb_s);
    stage_chunk(ht, row0, 1, 1, tid, xb_s);

    // per-warp group->output-row ids (warp-local: no block barrier needed)
    if (lane < 4)
        outrow[wrp * 4 + lane] = seg[row0 + wrp * 32 + lane * 8];

    unsigned long long hp[8];
    {
        const float2* b12 = (const float2*)b1;
        #pragma unroll
        for (int j = 0; j < 8; ++j) {
            float2 bv = b12[j];
            hp[j] = pack_xy(bv.x, bv.y);
        }
    }

    // ---- phase 1: 8 chunks (4 ht + 4 info), 3 buffers, 1 barrier/chunk ------
    #pragma unroll
    for (int cc = 0; cc < 8; ++cc) {
        if (cc < 7) cp_wait<1>(); else cp_wait<0>();
        __syncthreads();   // publishes chunk cc; certifies all warps did iter cc-1

        const int b = cc % NBUF;
        const float4* xb = xbuf4 + b * CHUNK_F4 + tid * CS;
        #pragma unroll
        for (int q2 = 0; q2 < 4; ++q2) {
            float4 v = xb[q2];
            float xs[4] = {v.x, v.y, v.z, v.w};
            #pragma unroll
            for (int c = 0; c < 4; ++c) {
                const int k = cc * 16 + q2 * 4 + c;   // weight row, compile-time
                unsigned long long xv = pack_dup(xs[c]);
                // constant-port loads: immediate address, warp-uniform
                const double2* wr = (const double2*)(cW1 + k * 16);
                double2 w01 = wr[0];
                double2 w23 = wr[1];
                ffma2(hp[0], xv, __double_as_longlong(w01.x));
                ffma2(hp[1], xv, __double_as_longlong(w01.y));
                ffma2(hp[2], xv, __double_as_longlong(w23.x));
                ffma2(hp[3], xv, __double_as_longlong(w23.y));
                double2 w45 = wr[2];
                double2 w67 = wr[3];
                ffma2(hp[4], xv, __double_as_longlong(w45.x));
                ffma2(hp[5], xv, __double_as_longlong(w45.y));
                ffma2(hp[6], xv, __double_as_longlong(w67.x));
                ffma2(hp[7], xv, __double_as_longlong(w67.y));
            }
        }
        // refill: buffer (cc+2)%3 held chunk cc-1, which every warp finished
        // before this iteration's barrier -> safe to overwrite now
        if (cc + 2 < 8)
            stage_chunk(cc + 2 < 4 ? ht : info, row0, cc + 2, (cc + 2) % NBUF,
                        tid, xb_s);
    }

    // ReLU + second layer -> score
    float score = b2[0];
    #pragma unroll
    for (int j = 0; j < 8; ++j) {
        float2 h2 = unpack2(hp[j]);
        score += fmaxf(h2.x, 0.f) * W2[2 * j]
               + fmaxf(h2.y, 0.f) * W2[2 * j + 1];
    }

    // ---- group-of-8 softmax (warp-aligned groups) -----------------------------
    float m = score;
    #pragma unroll
    for (int d = 1; d < 8; d <<= 1)
        m = fmaxf(m, __shfl_xor_sync(0xffffffffu, m, d));
    float e = __expf(score - m);
    float s = e;
    #pragma unroll
    for (int d = 1; d < 8; d <<= 1)
        s += __shfl_xor_sync(0xffffffffu, s, d);
    probs[tid] = e / s;

    __syncwarp();   // phase 2 below is warp-local (own rows, own probs, own outrow)

    // ---- phase 2: weighted pooling, float4 per lane (ht/info from L2) --------
    const int h = (tid >> 4) & 1;
    const int k = tid & 15;

    #pragma unroll
    for (int it = 0; it < 2; ++it) {
        const int gloc  = wrp * 4 + it * 2 + h;          // local group 0..15
        const int lbase = gloc * 8;
        const float4* hb = (const float4*)(ht   + (size_t)(row0 + lbase) * 64);
        const float4* ib = (const float4*)(info + (size_t)(row0 + lbase) * 64);
        const float4* fb = (const float4*)(fut  + (size_t)(row0 + lbase) * 64);

        float4 ah = make_float4(0.f, 0.f, 0.f, 0.f);
        float4 ai = ah, af = ah;
        #pragma unroll
        for (int j = 0; j < 8; ++j) {
            const float p = probs[lbase + j];
            float4 hv = hb[j * 16 + k];                   // L2 hit (phase-1 resident)
            float4 iv = ib[j * 16 + k];                   // L2 hit
            float4 fv = __ldcs(fb + j * 16 + k);          // single-use stream
            ah.x += p * hv.x; ah.y += p * hv.y; ah.z += p * hv.z; ah.w += p * hv.w;
            ai.x += p * iv.x; ai.y += p * iv.y; ai.z += p * iv.z; ai.w += p * iv.w;
            af.x += p * fv.x; af.y += p * fv.y; af.z += p * fv.z; af.w += p * fv.w;
        }
        float4* o4 = (float4*)(out + (size_t)outrow[gloc] * 192);
        o4[k]      = ah;
        o4[16 + k] = ai;
        o4[32 + k] = af;
    }
}

extern "C" void kernel_launch(void* const* d_in, const int* in_sizes, int n_in,
                              void* d_out, int out_size)
{
    const float* ht   = (const float*)d_in[0];
    const float* info = (const float*)d_in[1];
    const float* fut  = (const float*)d_in[2];
    const float* W1   = (const float*)d_in[3];
    const float* b1   = (const float*)d_in[4];
    const float* W2   = (const float*)d_in[5];
    const float* b2   = (const float*)d_in[6];
    const int*   seg  = (const int*)d_in[7];
    float* out = (float*)d_out;

    const int M = in_sizes[0] / 64;          // 262144
    const int nblocks = M / TPB;             // 2048

    static void* cw1_addr = nullptr;
    if (!cw1_addr) {
        cudaGetSymbolAddress(&cw1_addr, cW1);
        cudaFuncSetAttribute(lane_attn_kernel,
                             cudaFuncAttributeMaxDynamicSharedMemorySize, SMEM_BYTES);
    }

    // D2D async copy into the constant bank — one graph memcpy node
    cudaMemcpyAsync(cw1_addr, W1, 128 * 16 * sizeof(float), cudaMemcpyDeviceToDevice);

    lane_attn_kernel<<<nblocks, TPB, SMEM_BYTES>>>(ht, info, fut, b1, W2, b2, seg, out);
}

// round 11
// speedup vs baseline: 1.0219x; 1.0219x over previous
#include <cuda_runtime.h>
#include <cstdint>

// ---------------------------------------------------------------------------
// LaneAttention: per-lane MLP score -> per-group(8) softmax -> weighted pool
// M = 262144 lanes, groups of 8 contiguous lanes, N = 32768, out [N,192]
//
// R11 = R9 (TPB=128, grid=2048, 7 CTAs/SM, double-buffered cp.async staging,
// weights in constant bank, phase-2 pooling from L2) plus:
//   * final block barrier -> __syncwarp (phase 2 is warp-local)
//   * late L2 prefetch of this CTA's fut rows at chunk 5 (~2 chunks before
//     use) so tail fut reads are L2 hits without evicting the ht/info window
// ---------------------------------------------------------------------------

static constexpr int TPB = 128;        // threads = rows per block
static constexpr int CS  = 5;          // chunk-buffer row stride in float4 (4 data + 1 pad)
static constexpr int CHUNK_F4 = TPB * CS;            // 640 float4 per buffer

__constant__ float cW1[128 * 16];      // 8 KB

__device__ __forceinline__ unsigned long long pack_dup(float x) {
    unsigned long long r;
    asm("mov.b64 %0, {%1, %1};" : "=l"(r) : "f"(x));
    return r;
}
__device__ __forceinline__ unsigned long long pack_xy(float x, float y) {
    unsigned long long r;
    asm("mov.b64 %0, {%1, %2};" : "=l"(r) : "f"(x), "f"(y));
    return r;
}
__device__ __forceinline__ void ffma2(unsigned long long &d, unsigned long long a, unsigned long long b) {
    asm("fma.rn.f32x2 %0, %1, %2, %0;" : "+l"(d) : "l"(a), "l"(b));
}
__device__ __forceinline__ float2 unpack2(unsigned long long v) {
    float2 f;
    asm("mov.b64 {%0, %1}, %2;" : "=f"(f.x), "=f"(f.y) : "l"(v));
    return f;
}
__device__ __forceinline__ void cp_async16(uint32_t dst_smem, const void* src) {
    asm volatile("cp.async.cg.shared.global [%0], [%1], 16;\n"
                 :: "r"(dst_smem), "l"(src) : "memory");
}
__device__ __forceinline__ void cp_commit() {
    asm volatile("cp.async.commit_group;\n");
}
template <int N>
__device__ __forceinline__ void cp_wait() {
    asm volatile("cp.async.wait_group %0;\n" :: "n"(N) : "memory");
}

extern __shared__ float smem_f[];
// layout (floats): xbuf 2*640*4 = 5120 | probs 128 | outrow 16 ints
static constexpr int PROBS_OFF  = 2 * CHUNK_F4 * 4;                 // 5120
static constexpr int SMEM_BYTES = (PROBS_OFF + TPB) * 4 + 128;      // ~21.1 KB

// stage 16 columns (4 float4) of all 128 rows of `arr` chunk cc&3 into buffer b
__device__ __forceinline__ void stage_chunk(const float* arr, int row0, int cc,
                                            int b, int tid, uint32_t smem_base)
{
    const float4* src = (const float4*)(arr + (size_t)row0 * 64) + (cc & 3) * 4;
    #pragma unroll
    for (int u = 0; u < 4; ++u) {
        int f = tid + TPB * u;          // flat float4 idx 0..511
        int r = f >> 2, c = f & 3;
        cp_async16(smem_base + (uint32_t)(b * CHUNK_F4 + r * CS + c) * 16u,
                   src + r * 16 + c);
    }
    cp_commit();
}

__global__ __launch_bounds__(TPB, 7)
void lane_attn_kernel(const float* __restrict__ ht,
                      const float* __restrict__ info,
                      const float* __restrict__ fut,
                      const float* __restrict__ b1,   // [16]
                      const float* __restrict__ W2,   // [16]
                      const float* __restrict__ b2,   // [1]
                      const int*   __restrict__ seg,  // [M]
                      float* __restrict__ out)        // [N,192]
{
    float*  probs  = smem_f + PROBS_OFF;
    int*    outrow = (int*)(probs + TPB);
    const float4* xbuf4 = (const float4*)smem_f;

    const int tid  = threadIdx.x;
    const int wrp  = tid >> 5;
    const int lane = tid & 31;
    const int row0 = blockIdx.x * TPB;
    const uint32_t xb_s = (uint32_t)__cvta_generic_to_shared(smem_f);

    // kick off the staging pipeline immediately
    stage_chunk(ht, row0, 0, 0, tid, xb_s);
    stage_chunk(ht, row0, 1, 1, tid, xb_s);

    // per-warp group->output-row ids (phase 2 reads only this warp's entries)
    if (lane < 4)
        outrow[wrp * 4 + lane] = seg[row0 + wrp * 32 + lane * 8];

    unsigned long long hp[8];
    {
        const float2* b12 = (const float2*)b1;
        #pragma unroll
        for (int j = 0; j < 8; ++j) {
            float2 bv = b12[j];
            hp[j] = pack_xy(bv.x, bv.y);
        }
    }

    // ---- phase 1: 8 chunks (4 ht + 4 info), double-buffered ------------------
    #pragma unroll
    for (int cc = 0; cc < 8; ++cc) {
        if (cc < 7) cp_wait<1>(); else cp_wait<0>();
        __syncthreads();                      // staged data visible to all

        // late fut prefetch: ~2 chunks before phase 2 needs it (32 KB/CTA)
        if (cc == 5) {
            const char* fp = (const char*)(fut + (size_t)row0 * 64);
            asm volatile("prefetch.global.L2 [%0];" :: "l"(fp + (size_t)tid * 128));
            asm volatile("prefetch.global.L2 [%0];" :: "l"(fp + (size_t)(tid + TPB) * 128));
        }

        const int b = cc & 1;
        const float4* xb = xbuf4 + b * CHUNK_F4 + tid * CS;
        #pragma unroll
        for (int q2 = 0; q2 < 4; ++q2) {
            float4 v = xb[q2];
            float xs[4] = {v.x, v.y, v.z, v.w};
            #pragma unroll
            for (int c = 0; c < 4; ++c) {
                const int k = cc * 16 + q2 * 4 + c;   // weight row, compile-time
                unsigned long long xv = pack_dup(xs[c]);
                // constant-port loads: immediate address, warp-uniform
                const double2* wr = (const double2*)(cW1 + k * 16);
                double2 w01 = wr[0];
                double2 w23 = wr[1];
                ffma2(hp[0], xv, __double_as_longlong(w01.x));
                ffma2(hp[1], xv, __double_as_longlong(w01.y));
                ffma2(hp[2], xv, __double_as_longlong(w23.x));
                ffma2(hp[3], xv, __double_as_longlong(w23.y));
                double2 w45 = wr[2];
                double2 w67 = wr[3];
                ffma2(hp[4], xv, __double_as_longlong(w45.x));
                ffma2(hp[5], xv, __double_as_longlong(w45.y));
                ffma2(hp[6], xv, __double_as_longlong(w67.x));
                ffma2(hp[7], xv, __double_as_longlong(w67.y));
            }
        }
        __syncthreads();                      // all reads of buffer b done
        if (cc + 2 < 8)                        // refill the buffer just consumed
            stage_chunk(cc + 2 < 4 ? ht : info, row0, cc + 2, b, tid, xb_s);
    }

    // ReLU + second layer -> score
    float score = b2[0];
    #pragma unroll
    for (int j = 0; j < 8; ++j) {
        float2 h2 = unpack2(hp[j]);
        score += fmaxf(h2.x, 0.f) * W2[2 * j]
               + fmaxf(h2.y, 0.f) * W2[2 * j + 1];
    }

    // ---- group-of-8 softmax (warp-aligned groups) -----------------------------
    float m = score;
    #pragma unroll
    for (int d = 1; d < 8; d <<= 1)
        m = fmaxf(m, __shfl_xor_sync(0xffffffffu, m, d));
    float e = __expf(score - m);
    float s = e;
    #pragma unroll
    for (int d = 1; d < 8; d <<= 1)
        s += __shfl_xor_sync(0xffffffffu, s, d);
    probs[tid] = e / s;

    __syncwarp();   // phase 2 is warp-local: own rows, own probs, own outrow

    // ---- phase 2: weighted pooling, float4 per lane (all reads L2-warm) ------
    const int h = (tid >> 4) & 1;
    const int k = tid & 15;

    #pragma unroll
    for (int it = 0; it < 2; ++it) {
        const int gloc  = wrp * 4 + it * 2 + h;          // local group 0..15
        const int lbase = gloc * 8;
        const float4* hb = (const float4*)(ht   + (size_t)(row0 + lbase) * 64);
        const float4* ib = (const float4*)(info + (size_t)(row0 + lbase) * 64);
        const float4* fb = (const float4*)(fut  + (size_t)(row0 + lbase) * 64);

        float4 ah = make_float4(0.f, 0.f, 0.f, 0.f);
        float4 ai = ah, af = ah;
        #pragma unroll
        for (int j = 0; j < 8; ++j) {
            const float p = probs[lbase + j];
            float4 hv = hb[j * 16 + k];                   // L2 hit (phase-1 resident)
            float4 iv = ib[j * 16 + k];                   // L2 hit
            float4 fv = fb[j * 16 + k];                   // L2 hit (late prefetch)
            ah.x += p * hv.x; ah.y += p * hv.y; ah.z += p * hv.z; ah.w += p * hv.w;
            ai.x += p * iv.x; ai.y += p * iv.y; ai.z += p * iv.z; ai.w += p * iv.w;
            af.x += p * fv.x; af.y += p * fv.y; af.z += p * fv.z; af.w += p * fv.w;
        }
        float4* o4 = (float4*)(out + (size_t)outrow[gloc] * 192);
        o4[k]      = ah;
        o4[16 + k] = ai;
        o4[32 + k] = af;
    }
}

extern "C" void kernel_launch(void* const* d_in, const int* in_sizes, int n_in,
                              void* d_out, int out_size)
{
    const float* ht   = (const float*)d_in[0];
    const float* info = (const float*)d_in[1];
    const float* fut  = (const float*)d_in[2];
    const float* W1   = (const float*)d_in[3];
    const float* b1   = (const float*)d_in[4];
    const float* W2   = (const float*)d_in[5];
    const float* b2   = (const float*)d_in[6];
    const int*   seg  = (const int*)d_in[7];
    float* out = (float*)d_out;

    const int M = in_sizes[0] / 64;          // 262144
    const int nblocks = M / TPB;             // 2048

    static void* cw1_addr = nullptr;
    if (!cw1_addr) {
        cudaGetSymbolAddress(&cw1_addr, cW1);
        cudaFuncSetAttribute(lane_attn_kernel,
                             cudaFuncAttributeMaxDynamicSharedMemorySize, SMEM_BYTES);
    }

    // D2D async copy into the constant bank — one graph memcpy node
    cudaMemcpyAsync(cw1_addr, W1, 128 * 16 * sizeof(float), cudaMemcpyDeviceToDevice);

    lane_attn_kernel<<<nblocks, TPB, SMEM_BYTES>>>(ht, info, fut, b1, W2, b2, seg, out);
}

// round 12
// speedup vs baseline: 1.1757x; 1.1505x over previous
#include <cuda_runtime.h>
#include <cstdint>

// ---------------------------------------------------------------------------
// LaneAttention: per-lane MLP score -> per-group(8) softmax -> weighted pool
// M = 262144 lanes, groups of 8 contiguous lanes, N = 32768, out [N,192]
//
// R12 = R9 exactly (TPB=128, grid=2048, 7 CTAs/SM balanced 1.98 waves,
// double-buffered cp.async staging, weights in the constant bank, phase-2
// pooling from L2, __ldcs fut) with ONE isolated change: the final block
// barrier is now a __syncwarp — phase 2 is warp-local (per-warp outrow,
// own probs, own rows), so warps flow into pooling without re-converging.
// ---------------------------------------------------------------------------

static constexpr int TPB = 128;        // threads = rows per block
static constexpr int CS  = 5;          // chunk-buffer row stride in float4 (4 data + 1 pad)
static constexpr int CHUNK_F4 = TPB * CS;            // 640 float4 per buffer

__constant__ float cW1[128 * 16];      // 8 KB

__device__ __forceinline__ unsigned long long pack_dup(float x) {
    unsigned long long r;
    asm("mov.b64 %0, {%1, %1};" : "=l"(r) : "f"(x));
    return r;
}
__device__ __forceinline__ unsigned long long pack_xy(float x, float y) {
    unsigned long long r;
    asm("mov.b64 %0, {%1, %2};" : "=l"(r) : "f"(x), "f"(y));
    return r;
}
__device__ __forceinline__ void ffma2(unsigned long long &d, unsigned long long a, unsigned long long b) {
    asm("fma.rn.f32x2 %0, %1, %2, %0;" : "+l"(d) : "l"(a), "l"(b));
}
__device__ __forceinline__ float2 unpack2(unsigned long long v) {
    float2 f;
    asm("mov.b64 {%0, %1}, %2;" : "=f"(f.x), "=f"(f.y) : "l"(v));
    return f;
}
__device__ __forceinline__ void cp_async16(uint32_t dst_smem, const void* src) {
    asm volatile("cp.async.cg.shared.global [%0], [%1], 16;\n"
                 :: "r"(dst_smem), "l"(src) : "memory");
}
__device__ __forceinline__ void cp_commit() {
    asm volatile("cp.async.commit_group;\n");
}
template <int N>
__device__ __forceinline__ void cp_wait() {
    asm volatile("cp.async.wait_group %0;\n" :: "n"(N) : "memory");
}

extern __shared__ float smem_f[];
// layout (floats): xbuf 2*640*4 = 5120 | probs 128 | outrow 16 ints
static constexpr int PROBS_OFF  = 2 * CHUNK_F4 * 4;                 // 5120
static constexpr int SMEM_BYTES = (PROBS_OFF + TPB) * 4 + 128;      // ~21.1 KB

// stage 16 columns (4 float4) of all 128 rows of `arr` chunk cc&3 into buffer b
__device__ __forceinline__ void stage_chunk(const float* arr, int row0, int cc,
                                            int b, int tid, uint32_t smem_base)
{
    const float4* src = (const float4*)(arr + (size_t)row0 * 64) + (cc & 3) * 4;
    #pragma unroll
    for (int u = 0; u < 4; ++u) {
        int f = tid + TPB * u;          // flat float4 idx 0..511
        int r = f >> 2, c = f & 3;
        cp_async16(smem_base + (uint32_t)(b * CHUNK_F4 + r * CS + c) * 16u,
                   src + r * 16 + c);
    }
    cp_commit();
}

__global__ __launch_bounds__(TPB, 7)
void lane_attn_kernel(const float* __restrict__ ht,
                      const float* __restrict__ info,
                      const float* __restrict__ fut,
                      const float* __restrict__ b1,   // [16]
                      const float* __restrict__ W2,   // [16]
                      const float* __restrict__ b2,   // [1]
                      const int*   __restrict__ seg,  // [M]
                      float* __restrict__ out)        // [N,192]
{
    float*  probs  = smem_f + PROBS_OFF;
    int*    outrow = (int*)(probs + TPB);
    const float4* xbuf4 = (const float4*)smem_f;

    const int tid  = threadIdx.x;
    const int wrp  = tid >> 5;
    const int lane = tid & 31;
    const int row0 = blockIdx.x * TPB;
    const uint32_t xb_s = (uint32_t)__cvta_generic_to_shared(smem_f);

    // kick off the staging pipeline immediately
    stage_chunk(ht, row0, 0, 0, tid, xb_s);
    stage_chunk(ht, row0, 1, 1, tid, xb_s);

    // per-warp group->output-row ids (phase 2 reads only this warp's entries)
    if (lane < 4)
        outrow[wrp * 4 + lane] = seg[row0 + wrp * 32 + lane * 8];

    unsigned long long hp[8];
    {
        const float2* b12 = (const float2*)b1;
        #pragma unroll
        for (int j = 0; j < 8; ++j) {
            float2 bv = b12[j];
            hp[j] = pack_xy(bv.x, bv.y);
        }
    }

    // ---- phase 1: 8 chunks (4 ht + 4 info), double-buffered ------------------
    #pragma unroll
    for (int cc = 0; cc < 8; ++cc) {
        if (cc < 7) cp_wait<1>(); else cp_wait<0>();
        __syncthreads();                      // staged data visible to all

        const int b = cc & 1;
        const float4* xb = xbuf4 + b * CHUNK_F4 + tid * CS;
        #pragma unroll
        for (int q2 = 0; q2 < 4; ++q2) {
            float4 v = xb[q2];
            float xs[4] = {v.x, v.y, v.z, v.w};
            #pragma unroll
            for (int c = 0; c < 4; ++c) {
                const int k = cc * 16 + q2 * 4 + c;   // weight row, compile-time
                unsigned long long xv = pack_dup(xs[c]);
                // constant-port loads: immediate address, warp-uniform
                const double2* wr = (const double2*)(cW1 + k * 16);
                double2 w01 = wr[0];
                double2 w23 = wr[1];
                ffma2(hp[0], xv, __double_as_longlong(w01.x));
                ffma2(hp[1], xv, __double_as_longlong(w01.y));
                ffma2(hp[2], xv, __double_as_longlong(w23.x));
                ffma2(hp[3], xv, __double_as_longlong(w23.y));
                double2 w45 = wr[2];
                double2 w67 = wr[3];
                ffma2(hp[4], xv, __double_as_longlong(w45.x));
                ffma2(hp[5], xv, __double_as_longlong(w45.y));
                ffma2(hp[6], xv, __double_as_longlong(w67.x));
                ffma2(hp[7], xv, __double_as_longlong(w67.y));
            }
        }
        __syncthreads();                      // all reads of buffer b done
        if (cc + 2 < 8)                        // refill the buffer just consumed
            stage_chunk(cc + 2 < 4 ? ht : info, row0, cc + 2, b, tid, xb_s);
    }

    // ReLU + second layer -> score
    float score = b2[0];
    #pragma unroll
    for (int j = 0; j < 8; ++j) {
        float2 h2 = unpack2(hp[j]);
        score += fmaxf(h2.x, 0.f) * W2[2 * j]
               + fmaxf(h2.y, 0.f) * W2[2 * j + 1];
    }

    // ---- group-of-8 softmax (warp-aligned groups) -----------------------------
    float m = score;
    #pragma unroll
    for (int d = 1; d < 8; d <<= 1)
        m = fmaxf(m, __shfl_xor_sync(0xffffffffu, m, d));
    float e = __expf(score - m);
    float s = e;
    #pragma unroll
    for (int d = 1; d < 8; d <<= 1)
        s += __shfl_xor_sync(0xffffffffu, s, d);
    probs[tid] = e / s;

    __syncwarp();   // phase 2 is warp-local: own rows, own probs, own outrow

    // ---- phase 2: weighted pooling, float4 per lane (ht/info from L2) --------
    const int h = (tid >> 4) & 1;
    const int k = tid & 15;

    #pragma unroll
    for (int it = 0; it < 2; ++it) {
        const int gloc  = wrp * 4 + it * 2 + h;          // local group 0..15
        const int lbase = gloc * 8;
        const float4* hb = (const float4*)(ht   + (size_t)(row0 + lbase) * 64);
        const float4* ib = (const float4*)(info + (size_t)(row0 + lbase) * 64);
        const float4* fb = (const float4*)(fut  + (size_t)(row0 + lbase) * 64);

        float4 ah = make_float4(0.f, 0.f, 0.f, 0.f);
        float4 ai = ah, af = ah;
        #pragma unroll
        for (int j = 0; j < 8; ++j) {
            const float p = probs[lbase + j];
            float4 hv = hb[j * 16 + k];                   // L2 hit (phase-1 resident)
            float4 iv = ib[j * 16 + k];                   // L2 hit
            float4 fv = __ldcs(fb + j * 16 + k);          // single-use stream
            ah.x += p * hv.x; ah.y += p * hv.y; ah.z += p * hv.z; ah.w += p * hv.w;
            ai.x += p * iv.x; ai.y += p * iv.y; ai.z += p * iv.z; ai.w += p * iv.w;
            af.x += p * fv.x; af.y += p * fv.y; af.z += p * fv.z; af.w += p * fv.w;
        }
        float4* o4 = (float4*)(out + (size_t)outrow[gloc] * 192);
        o4[k]      = ah;
        o4[16 + k] = ai;
        o4[32 + k] = af;
    }
}

extern "C" void kernel_launch(void* const* d_in, const int* in_sizes, int n_in,
                              void* d_out, int out_size)
{
    const float* ht   = (const float*)d_in[0];
    const float* info = (const float*)d_in[1];
    const float* fut  = (const float*)d_in[2];
    const float* W1   = (const float*)d_in[3];
    const float* b1   = (const float*)d_in[4];
    const float* W2   = (const float*)d_in[5];
    const float* b2   = (const float*)d_in[6];
    const int*   seg  = (const int*)d_in[7];
    float* out = (float*)d_out;

    const int M = in_sizes[0] / 64;          // 262144
    const int nblocks = M / TPB;             // 2048

    static void* cw1_addr = nullptr;
    if (!cw1_addr) {
        cudaGetSymbolAddress(&cw1_addr, cW1);
        cudaFuncSetAttribute(lane_attn_kernel,
                             cudaFuncAttributeMaxDynamicSharedMemorySize, SMEM_BYTES);
    }

    // D2D async copy into the constant bank — one graph memcpy node
    cudaMemcpyAsync(cw1_addr, W1, 128 * 16 * sizeof(float), cudaMemcpyDeviceToDevice);

    lane_attn_kernel<<<nblocks, TPB, SMEM_BYTES>>>(ht, info, fut, b1, W2, b2, seg, out);
}